// round 13
// baseline (speedup 1.0000x reference)
#include <cuda_runtime.h>
#include <cuda_bf16.h>
#include <cuda_fp16.h>
#include <math.h>
#include <stdint.h>

// ---------------- problem constants ----------------
#define MROWS   400000
#define NBAG    8
#define NPER    50000
#define DIN     256
#define HDIM    128
#define INV_TAU (1.0f/0.3f)
#define LN_EPS  1e-5f
#define CHUNK   256
#define NCHUNK3 196              // ceil(50000/256)

// ---------------- scratch globals ----------------
__device__ __half g_h2h[(size_t)MROWS * HDIM];          // 102.4 MB (fp16)
__device__ float g_scores[MROWS];
__device__ uint32_t g_bagmaxi[NBAG];                    // order-preserving uint max
__device__ float g_pvec[NBAG * NCHUNK3 * HDIM];
__device__ float g_pZ[NBAG * NCHUNK3];
// fp16 hi/lo weights, dense [n][k]: [W1half0, W1half1, W2, Wa1] x [hi 32KB | lo 32KB]
__device__ __align__(16) unsigned char g_wsw[4 * 65536];

// ---------------- smem layout (bytes), single CTA = 73808 -> 2 CTAs/SM ----------------
#define B_HI_OFF  0              // weight buffer hi [128][136] fp16
#define BLO       34816          // hi -> lo offset
#define BIAS_OFF  69632          // 1025 floats (4100 B)
#define RED2_OFF  73744          // 16 floats: per-warp [lo,hi] score maxima
#define SMEM_SZ   73808

__device__ __forceinline__ uint32_t smem_to_u32(const void* p) {
    uint32_t a;
    asm("{ .reg .u64 t; cvta.to.shared.u64 t, %1; cvt.u32.u64 %0, t; }" : "=r"(a) : "l"(p));
    return a;
}

#define LDM4(r, addr) \
    asm volatile("ldmatrix.sync.aligned.m8n8.x4.shared.b16 {%0,%1,%2,%3}, [%4];" \
        : "=r"((r)[0]), "=r"((r)[1]), "=r"((r)[2]), "=r"((r)[3]) : "r"(addr))

#define MMA16816(c, a, b0, b1) \
    asm volatile("mma.sync.aligned.m16n8k16.row.col.f32.f16.f16.f32 " \
        "{%0,%1,%2,%3}, {%4,%5,%6,%7}, {%8,%9}, {%0,%1,%2,%3};" \
        : "+f"((c)[0]), "+f"((c)[1]), "+f"((c)[2]), "+f"((c)[3]) \
        : "r"((a)[0]), "r"((a)[1]), "r"((a)[2]), "r"((a)[3]), "r"(b0), "r"(b1))

#define CP_ASYNC16(saddr, gptr) \
    asm volatile("cp.async.ca.shared.global [%0], [%1], 16;" :: "r"(saddr), "l"(gptr) : "memory")
#define CP_COMMIT() asm volatile("cp.async.commit_group;" ::: "memory")
#define CP_WAIT(n)  asm volatile("cp.async.wait_group %0;" :: "n"(n) : "memory")

__device__ __forceinline__ float fast_tanh(float x) {
    float e = __expf(2.0f * x);
    return 1.0f - __fdividef(2.0f, e + 1.0f);
}
__device__ __forceinline__ uint32_t pack_h2(float a, float b) {
    __half2 h = __floats2half2_rn(a, b);
    return *(uint32_t*)&h;
}
// order-preserving float->uint key (monotonic): max over keys == max over floats
__device__ __forceinline__ uint32_t fkey(float f) {
    uint32_t u = __float_as_uint(f);
    return (u & 0x80000000u) ? ~u : (u | 0x80000000u);
}
__device__ __forceinline__ float funkey(uint32_t k) {
    return (k & 0x80000000u) ? __uint_as_float(k & 0x7FFFFFFFu) : __uint_as_float(~k);
}

// ---------------- weight prep: fp32 -> dense fp16 hi/lo [n][k]; reset bagmax ----------------
__global__ void k_prep(const float* __restrict__ W1, const float* __restrict__ W2,
                       const float* __restrict__ Wa1)
{
    if (blockIdx.x == 0 && threadIdx.x < NBAG) g_bagmaxi[threadIdx.x] = 0u;
    int mat = blockIdx.x;
    const float* W; int koff;
    if (mat == 0)      { W = W1;  koff = 0;   }
    else if (mat == 1) { W = W1;  koff = 128; }
    else if (mat == 2) { W = W2;  koff = 0;   }
    else               { W = Wa1; koff = 0;   }
    __half* dh = (__half*)(g_wsw + (size_t)mat * 65536);
    __half* dl = dh + 16384;
    for (int idx = threadIdx.x; idx < 16384; idx += blockDim.x) {
        int n = idx >> 7, k = idx & 127;
        float w = W[(size_t)(koff + k) * 128 + n];   // B[n][k] = W[k][n]
        __half h = __float2half_rn(w);
        __half l = __float2half_rn(w - __half2float(h));
        dh[n * 128 + k] = h;
        dl[n * 128 + k] = l;
    }
}

// ---------------- staging ----------------
__device__ __forceinline__ void stage_w_async(uint32_t smb, int mat, int tid) {
    const unsigned char* src = g_wsw + (size_t)mat * 65536;
    unsigned long long gbase = (unsigned long long)__cvta_generic_to_global((void*)src);
#pragma unroll
    for (int i = 0; i < 8; i++) {
        int idx = tid + i * 256;
        int r = idx >> 4, q = idx & 15;
        uint32_t soff = (uint32_t)(r * 136 + q * 8) * 2u;
        unsigned long long goff = (unsigned long long)(r * 128 + q * 8) * 2ull;
        CP_ASYNC16(smb + B_HI_OFF + soff,       gbase + goff);
        CP_ASYNC16(smb + B_HI_OFF + BLO + soff, gbase + 32768ull + goff);
    }
}
__device__ __forceinline__ void stage_w_async_hi(uint32_t smb, int mat, int tid) {
    const unsigned char* src = g_wsw + (size_t)mat * 65536;
    unsigned long long gbase = (unsigned long long)__cvta_generic_to_global((void*)src);
#pragma unroll
    for (int i = 0; i < 8; i++) {
        int idx = tid + i * 256;
        int r = idx >> 4, q = idx & 15;
        uint32_t soff = (uint32_t)(r * 136 + q * 8) * 2u;
        unsigned long long goff = (unsigned long long)(r * 128 + q * 8) * 2ull;
        CP_ASYNC16(smb + B_HI_OFF + soff, gbase + goff);
    }
}

// ---------------- inners (explicit B prefetch) ----------------
// 2-pass (B hi + lo) — phase 2 only
__device__ __forceinline__ void mma_inner(uint32_t smb, uint32_t bRow, uint32_t bK0, int ks,
                                          const uint32_t* a, float (*acc)[4]) {
    uint32_t base = smb + B_HI_OFF + (bRow + bK0 + (uint32_t)ks * 16u) * 2u;
    uint32_t bh[4], bl[4];
    LDM4(bh, base);
    LDM4(bl, base + BLO);
#pragma unroll
    for (int nt2 = 0; nt2 < 8; nt2++) {
        uint32_t nh[4], nl[4];
        if (nt2 < 7) {
            uint32_t naddr = base + (uint32_t)(nt2 + 1) * (16u * 136u * 2u);
            LDM4(nh, naddr);
            LDM4(nl, naddr + BLO);
        }
        MMA16816(acc[2 * nt2],     a, bh[0], bh[1]);
        MMA16816(acc[2 * nt2 + 1], a, bh[2], bh[3]);
        MMA16816(acc[2 * nt2],     a, bl[0], bl[1]);
        MMA16816(acc[2 * nt2 + 1], a, bl[2], bl[3]);
        if (nt2 < 7) {
#pragma unroll
            for (int j = 0; j < 4; j++) { bh[j] = nh[j]; bl[j] = nl[j]; }
        }
    }
}
// single-pass (B hi only) — phases 1, 3
__device__ __forceinline__ void mma_inner_hi(uint32_t smb, uint32_t bRow, uint32_t bK0, int ks,
                                             const uint32_t* a, float (*acc)[4]) {
    uint32_t base = smb + B_HI_OFF + (bRow + bK0 + (uint32_t)ks * 16u) * 2u;
    uint32_t bh[4];
    LDM4(bh, base);
#pragma unroll
    for (int nt2 = 0; nt2 < 8; nt2++) {
        uint32_t nh[4];
        if (nt2 < 7) {
            LDM4(nh, base + (uint32_t)(nt2 + 1) * (16u * 136u * 2u));
        }
        MMA16816(acc[2 * nt2],     a, bh[0], bh[1]);
        MMA16816(acc[2 * nt2 + 1], a, bh[2], bh[3]);
        if (nt2 < 7) {
#pragma unroll
            for (int j = 0; j < 4; j++) bh[j] = nh[j];
        }
    }
}

// phase-1 block: A straight from gmem x, depth-2 software pipeline
__device__ __forceinline__ void mma_block_g(uint32_t smb, const float* __restrict__ x,
                                            size_t rowTile, int hh, int w, int L,
                                            float (*acc)[4]) {
    const int g = L >> 2, t = L & 3;
    const float* p0 = x + (rowTile + (size_t)(w * 16 + g)) * DIN + hh * 128 + 2 * t;
    const float* p1 = p0 + 8 * DIN;
    const int g3 = L >> 3, rr = L & 7;
    const uint32_t bRow = (uint32_t)((g3 >> 1) * 8 + rr) * 136u;
    const uint32_t bK0  = 8u * (uint32_t)(g3 & 1);

    float2 buf[2][4];
#pragma unroll
    for (int s = 0; s < 2; s++) {
        buf[s][0] = *(const float2*)(p0 + s * 16);
        buf[s][1] = *(const float2*)(p1 + s * 16);
        buf[s][2] = *(const float2*)(p0 + s * 16 + 8);
        buf[s][3] = *(const float2*)(p1 + s * 16 + 8);
    }
#pragma unroll
    for (int ks = 0; ks < 8; ks++) {
        float2 n0, n1, n2, n3;
        if (ks < 6) {
            n0 = *(const float2*)(p0 + (ks + 2) * 16);
            n1 = *(const float2*)(p1 + (ks + 2) * 16);
            n2 = *(const float2*)(p0 + (ks + 2) * 16 + 8);
            n3 = *(const float2*)(p1 + (ks + 2) * 16 + 8);
        }
        const int s = ks & 1;
        uint32_t a[4];
        a[0] = pack_h2(buf[s][0].x, buf[s][0].y);
        a[1] = pack_h2(buf[s][1].x, buf[s][1].y);
        a[2] = pack_h2(buf[s][2].x, buf[s][2].y);
        a[3] = pack_h2(buf[s][3].x, buf[s][3].y);
        mma_inner_hi(smb, bRow, bK0, ks, a, acc);
        if (ks < 6) { buf[s][0] = n0; buf[s][1] = n1; buf[s][2] = n2; buf[s][3] = n3; }
    }
}

// phase-2 block: A from regs, 2-pass B
__device__ __forceinline__ void mma_block_r(uint32_t smb, const uint32_t* afh, int L,
                                            float (*acc)[4]) {
    const int g3 = L >> 3, rr = L & 7;
    const uint32_t bRow = (uint32_t)((g3 >> 1) * 8 + rr) * 136u;
    const uint32_t bK0  = 8u * (uint32_t)(g3 & 1);
#pragma unroll 2
    for (int ks = 0; ks < 8; ks++)
        mma_inner(smb, bRow, bK0, ks, afh + ks * 4, acc);
}
// phase-3 block: A from regs, single-pass B
__device__ __forceinline__ void mma_block_r1(uint32_t smb, const uint32_t* afh, int L,
                                             float (*acc)[4]) {
    const int g3 = L >> 3, rr = L & 7;
    const uint32_t bRow = (uint32_t)((g3 >> 1) * 8 + rr) * 136u;
    const uint32_t bK0  = 8u * (uint32_t)(g3 & 1);
#pragma unroll 2
    for (int ks = 0; ks < 8; ks++)
        mma_inner_hi(smb, bRow, bK0, ks, afh + ks * 4, acc);
}

__device__ __forceinline__ void repack_A(float (*acc)[4], uint32_t* afh) {
#pragma unroll
    for (int j = 0; j < 8; j++) {
        afh[4 * j]     = pack_h2(acc[2 * j][0],     acc[2 * j][1]);
        afh[4 * j + 1] = pack_h2(acc[2 * j][2],     acc[2 * j][3]);
        afh[4 * j + 2] = pack_h2(acc[2 * j + 1][0], acc[2 * j + 1][1]);
        afh[4 * j + 3] = pack_h2(acc[2 * j + 1][2], acc[2 * j + 1][3]);
    }
}

// ---------------- LN + ReLU epilogue (full row per warp, shuffle-only) ----------------
__device__ __forceinline__ void ln_relu(float (*acc)[4], const float* bias, int boff, int L) {
    const int q2 = 2 * (L & 3);
    float s0 = 0.f, s1 = 0.f;
#pragma unroll
    for (int nt = 0; nt < 16; nt++) {
        int c = nt * 8 + q2;
        float b0 = bias[boff + c], b1v = bias[boff + c + 1];
        acc[nt][0] += b0; acc[nt][1] += b1v; acc[nt][2] += b0; acc[nt][3] += b1v;
        s0 += acc[nt][0] + acc[nt][1];
        s1 += acc[nt][2] + acc[nt][3];
    }
    s0 += __shfl_xor_sync(0xffffffffu, s0, 1); s0 += __shfl_xor_sync(0xffffffffu, s0, 2);
    s1 += __shfl_xor_sync(0xffffffffu, s1, 1); s1 += __shfl_xor_sync(0xffffffffu, s1, 2);
    float mu0 = s0 * 0.0078125f, mu1 = s1 * 0.0078125f;
    float v0 = 0.f, v1 = 0.f;
#pragma unroll
    for (int nt = 0; nt < 16; nt++) {
        float d;
        d = acc[nt][0] - mu0; v0 = fmaf(d, d, v0);
        d = acc[nt][1] - mu0; v0 = fmaf(d, d, v0);
        d = acc[nt][2] - mu1; v1 = fmaf(d, d, v1);
        d = acc[nt][3] - mu1; v1 = fmaf(d, d, v1);
    }
    v0 += __shfl_xor_sync(0xffffffffu, v0, 1); v0 += __shfl_xor_sync(0xffffffffu, v0, 2);
    v1 += __shfl_xor_sync(0xffffffffu, v1, 1); v1 += __shfl_xor_sync(0xffffffffu, v1, 2);
    float i0 = rsqrtf(fmaf(v0, 0.0078125f, LN_EPS));
    float i1 = rsqrtf(fmaf(v1, 0.0078125f, LN_EPS));
#pragma unroll
    for (int nt = 0; nt < 16; nt++) {
        int c = nt * 8 + q2;
        float g0 = bias[boff + 128 + c], g1v = bias[boff + 128 + c + 1];
        float e0 = bias[boff + 256 + c], e1v = bias[boff + 256 + c + 1];
        acc[nt][0] = fmaxf(fmaf((acc[nt][0] - mu0) * i0, g0, e0), 0.f);
        acc[nt][1] = fmaxf(fmaf((acc[nt][1] - mu0) * i0, g1v, e1v), 0.f);
        acc[nt][2] = fmaxf(fmaf((acc[nt][2] - mu1) * i1, g0, e0), 0.f);
        acc[nt][3] = fmaxf(fmaf((acc[nt][3] - mu1) * i1, g1v, e1v), 0.f);
    }
}

// ---------------- fused row kernel (2 CTAs/SM) ----------------
__global__ void __launch_bounds__(256, 2)
k_rows_mma(const float* __restrict__ x,
           const float* __restrict__ b1, const float* __restrict__ g1, const float* __restrict__ be1,
           const float* __restrict__ b2, const float* __restrict__ g2, const float* __restrict__ be2,
           const float* __restrict__ ba1, const float* __restrict__ ba2, const float* __restrict__ Wa2)
{
    extern __shared__ char sm[];
    const uint32_t smb = smem_to_u32(sm);
    const int tid = threadIdx.x;
    const int w = tid >> 5, L = tid & 31;
    const size_t rowTile = (size_t)blockIdx.x * 128;
    float* bias = (float*)(sm + BIAS_OFF);
    float* red2 = (float*)(sm + RED2_OFF);

    stage_w_async_hi(smb, 0, tid); CP_COMMIT();   // W1 half0 (hi only)

    if (tid < 128) {
        bias[tid]       = b1[tid];  bias[128 + tid] = g1[tid];  bias[256 + tid] = be1[tid];
        bias[384 + tid] = b2[tid];  bias[512 + tid] = g2[tid];  bias[640 + tid] = be2[tid];
        bias[768 + tid] = ba1[tid]; bias[896 + tid] = Wa2[tid];
    }
    if (tid == 0) bias[1024] = ba2[0];

    float acc[16][4];
#pragma unroll
    for (int nt = 0; nt < 16; nt++)
#pragma unroll
        for (int j = 0; j < 4; j++) acc[nt][j] = 0.f;

    // ===== PHASE 1: x @ W1 (hi-only; A from gmem, depth-2 pipeline) =====
    CP_WAIT(0);
    __syncthreads();
    mma_block_g(smb, x, rowTile, 0, w, L, acc);
    __syncthreads();
    stage_w_async_hi(smb, 1, tid); CP_COMMIT();   // W1 half1 (hi only)
    CP_WAIT(0);
    __syncthreads();
    mma_block_g(smb, x, rowTile, 1, w, L, acc);
    __syncthreads();
    stage_w_async(smb, 2, tid); CP_COMMIT();      // W2 hi+lo (overlaps LN1)

    uint32_t afh[32];
    ln_relu(acc, bias, 0, L);
    repack_A(acc, afh);
    CP_WAIT(0);
    __syncthreads();

    // ===== PHASE 2: h1 @ W2 (2-pass: precision-critical, feeds bag average) =====
#pragma unroll
    for (int nt = 0; nt < 16; nt++)
#pragma unroll
        for (int j = 0; j < 4; j++) acc[nt][j] = 0.f;
    mma_block_r(smb, afh, L, acc);
    __syncthreads();
    stage_w_async_hi(smb, 3, tid); CP_COMMIT();   // Wa1 hi (overlaps LN2 + h2 store)

    ln_relu(acc, bias, 384, L);
    // h2 -> gmem fp16, direct from fragments
    {
        const int r0 = w * 16 + (L >> 2), r1 = r0 + 8;
        const int q2 = 2 * (L & 3);
        __half* h0p = g_h2h + (rowTile + r0) * HDIM;
        __half* h1p = g_h2h + (rowTile + r1) * HDIM;
#pragma unroll
        for (int nt = 0; nt < 16; nt++) {
            int c = nt * 8 + q2;
            *(uint32_t*)(h0p + c) = pack_h2(acc[nt][0], acc[nt][1]);
            *(uint32_t*)(h1p + c) = pack_h2(acc[nt][2], acc[nt][3]);
        }
    }
    repack_A(acc, afh);
    CP_WAIT(0);
    __syncthreads();

    // ===== PHASE 3: h2 @ Wa1 (hi-only) -> tanh -> dot Wa2 -> scores + fused bag max =====
#pragma unroll
    for (int nt = 0; nt < 16; nt++)
#pragma unroll
        for (int j = 0; j < 4; j++) acc[nt][j] = 0.f;
    mma_block_r1(smb, afh, L, acc);

    {
        const int r0 = w * 16 + (L >> 2), r1 = r0 + 8;
        const int q2 = 2 * (L & 3);
        float p0 = 0.f, p1 = 0.f;
#pragma unroll
        for (int nt = 0; nt < 16; nt++) {
            int c = nt * 8 + q2;
            float wa0 = bias[896 + c], wa1v = bias[896 + c + 1];
            float bb0 = bias[768 + c], bb1 = bias[768 + c + 1];
            p0 = fmaf(fast_tanh(acc[nt][0] + bb0), wa0, p0);
            p0 = fmaf(fast_tanh(acc[nt][1] + bb1), wa1v, p0);
            p1 = fmaf(fast_tanh(acc[nt][2] + bb0), wa0, p1);
            p1 = fmaf(fast_tanh(acc[nt][3] + bb1), wa1v, p1);
        }
        p0 += __shfl_xor_sync(0xffffffffu, p0, 1); p0 += __shfl_xor_sync(0xffffffffu, p0, 2);
        p1 += __shfl_xor_sync(0xffffffffu, p1, 1); p1 += __shfl_xor_sync(0xffffffffu, p1, 2);
        const float bb = bias[1024];
        const float s0v = p0 + bb, s1v = p1 + bb;
        if ((L & 3) == 0) {
            g_scores[rowTile + r0] = s0v;
            g_scores[rowTile + r1] = s1v;
        }
        // fused per-bag max (deterministic: pure max reduction + atomicMax on keys)
        const int bagB = (int)((rowTile + 127) / NPER);
        const size_t boundary = (size_t)bagB * NPER;   // rows >= boundary belong to bagB
        float mlo = -3.4e38f, mhi = -3.4e38f;
        if (rowTile + r0 >= boundary) mhi = fmaxf(mhi, s0v); else mlo = fmaxf(mlo, s0v);
        if (rowTile + r1 >= boundary) mhi = fmaxf(mhi, s1v); else mlo = fmaxf(mlo, s1v);
#pragma unroll
        for (int off = 16; off; off >>= 1) {
            mlo = fmaxf(mlo, __shfl_xor_sync(0xffffffffu, mlo, off));
            mhi = fmaxf(mhi, __shfl_xor_sync(0xffffffffu, mhi, off));
        }
        if (L == 0) { red2[w * 2] = mlo; red2[w * 2 + 1] = mhi; }
        __syncthreads();
        if (tid == 0) {
            float Mlo = -3.4e38f, Mhi = -3.4e38f;
#pragma unroll
            for (int q = 0; q < 8; q++) {
                Mlo = fmaxf(Mlo, red2[q * 2]);
                Mhi = fmaxf(Mhi, red2[q * 2 + 1]);
            }
            const int bagA = (int)(rowTile / NPER);
            if (bagA != bagB) {
                atomicMax(&g_bagmaxi[bagA], fkey(Mlo));
                atomicMax(&g_bagmaxi[bagB], fkey(Mhi));
            } else {
                atomicMax(&g_bagmaxi[bagA], fkey(fmaxf(Mlo, Mhi)));
            }
        }
    }
}

// ---------------- weighted partial sums (chunks of 256 rows, fp16 h2, MLP 8) ----------------
__global__ __launch_bounds__(256)
void k_wsum()
{
    const int b = blockIdx.x / NCHUNK3;
    const int c = blockIdx.x % NCHUNK3;
    const int tid = threadIdx.x;
    const int base = c * CHUNK;
    const int cnt = min(CHUNK, NPER - base);
    __shared__ float wrow[CHUNK];
    __shared__ float2 sred[256];

    const float bm = funkey(g_bagmaxi[b]);
    wrow[tid] = (tid < cnt) ? expf((g_scores[(size_t)b * NPER + base + tid] - bm) * INV_TAU) : 0.f;
    __syncthreads();

    const int c2 = tid & 63;
    const int rg = tid >> 6;
    const uint32_t* hp = (const uint32_t*)(g_h2h + ((size_t)b * NPER + base) * HDIM) + c2;

    float2 a0 = {0.f,0.f}, a1 = {0.f,0.f}, a2 = {0.f,0.f}, a3 = {0.f,0.f};
    int n = rg;
    for (; n + 28 < cnt; n += 32) {
        uint32_t u[8];
#pragma unroll
        for (int j = 0; j < 8; j++) u[j] = hp[(size_t)(n + 4 * j) * 64];
#pragma unroll
        for (int j = 0; j < 8; j += 4) {
            float2 f0 = __half22float2(*(const __half2*)&u[j]);
            float2 f1 = __half22float2(*(const __half2*)&u[j + 1]);
            float2 f2 = __half22float2(*(const __half2*)&u[j + 2]);
            float2 f3 = __half22float2(*(const __half2*)&u[j + 3]);
            float w0 = wrow[n + 4 * j], w1 = wrow[n + 4 * j + 4];
            float w2 = wrow[n + 4 * j + 8], w3 = wrow[n + 4 * j + 12];
            a0.x = fmaf(w0, f0.x, a0.x); a0.y = fmaf(w0, f0.y, a0.y);
            a1.x = fmaf(w1, f1.x, a1.x); a1.y = fmaf(w1, f1.y, a1.y);
            a2.x = fmaf(w2, f2.x, a2.x); a2.y = fmaf(w2, f2.y, a2.y);
            a3.x = fmaf(w3, f3.x, a3.x); a3.y = fmaf(w3, f3.y, a3.y);
        }
    }
    for (; n < cnt; n += 4) {
        uint32_t u = hp[(size_t)n * 64];
        float2 f = __half22float2(*(const __half2*)&u);
        float wv = wrow[n];
        a0.x = fmaf(wv, f.x, a0.x); a0.y = fmaf(wv, f.y, a0.y);
    }
    float2 at;
    at.x = (a0.x + a1.x) + (a2.x + a3.x);
    at.y = (a0.y + a1.y) + (a2.y + a3.y);
    sred[tid] = at;
    __syncthreads();
    if (tid < 64) {
        float2 t0 = sred[tid], t1 = sred[tid + 64], t2 = sred[tid + 128], t3 = sred[tid + 192];
        float* pv = g_pvec + ((size_t)b * NCHUNK3 + c) * HDIM;
        pv[2 * tid]     = (t0.x + t1.x) + (t2.x + t3.x);
        pv[2 * tid + 1] = (t0.y + t1.y) + (t2.y + t3.y);
    }

    __syncthreads();
    float z = wrow[tid];
    wrow[tid] = z;
    __syncthreads();
    for (int off = 128; off; off >>= 1) {
        if (tid < off) wrow[tid] += wrow[tid + off];
        __syncthreads();
    }
    if (tid == 0) g_pZ[b * NCHUNK3 + c] = wrow[0];
}

// ---------------- final heads ----------------
__global__ __launch_bounds__(128)
void k_final(const float* __restrict__ Wc1, const float* __restrict__ bc1,
             const float* __restrict__ Wc2, const float* __restrict__ bc2,
             const float* __restrict__ Ws1, const float* __restrict__ bs1,
             const float* __restrict__ Ws2, const float* __restrict__ bs2,
             float* __restrict__ out)
{
    const int bag = blockIdx.x;
    const int tid = threadIdx.x;
    __shared__ float bagn[128];
    __shared__ float hid[128];
    __shared__ float redz[128];
    __shared__ float hs[64];

    float vv = 0.0f;
    for (int c = 0; c < NCHUNK3; c++)
        vv += g_pvec[((size_t)bag * NCHUNK3 + c) * HDIM + tid];

    float zp = 0.0f;
    for (int c = tid; c < NCHUNK3; c += 128)
        zp += g_pZ[bag * NCHUNK3 + c];
    redz[tid] = zp;
    __syncthreads();
    for (int off = 64; off; off >>= 1) {
        if (tid < off) redz[tid] += redz[tid + off];
        __syncthreads();
    }
    const float Z = redz[0];
    bagn[tid] = vv / Z;
    __syncthreads();

    {
        float h = bc1[tid];
        for (int k = 0; k < 128; k++) h = fmaf(bagn[k], Wc1[k * 128 + tid], h);
        hid[tid] = fmaxf(h, 0.0f);
    }
    if (tid < 64) {
        float h = bs1[tid];
        for (int k = 0; k < 128; k++) h = fmaf(bagn[k], Ws1[k * 64 + tid], h);
        hs[tid] = fmaxf(h, 0.0f);
    }
    __syncthreads();

    if (tid < 2) {
        float s = bc2[tid];
        for (int j = 0; j < 128; j++) s = fmaf(hid[j], Wc2[j * 2 + tid], s);
        out[bag * 2 + tid] = s;
    }
    if (tid == 2) {
        float r = bs2[0];
        for (int j = 0; j < 64; j++) r = fmaf(hs[j], Ws2[j], r);
        out[16 + bag] = r;
    }
}

extern "C" void kernel_launch(void* const* d_in, const int* in_sizes, int n_in,
                              void* d_out, int out_size)
{
    const float* x   = (const float*)d_in[0];
    const float* W1  = (const float*)d_in[1];
    const float* b1  = (const float*)d_in[2];
    const float* g1  = (const float*)d_in[3];
    const float* be1 = (const float*)d_in[4];
    const float* W2  = (const float*)d_in[5];
    const float* b2  = (const float*)d_in[6];
    const float* g2  = (const float*)d_in[7];
    const float* be2 = (const float*)d_in[8];
    const float* Wa1 = (const float*)d_in[9];
    const float* ba1 = (const float*)d_in[10];
    const float* Wa2 = (const float*)d_in[11];
    const float* ba2 = (const float*)d_in[12];
    const float* Wc1 = (const float*)d_in[13];
    const float* bc1 = (const float*)d_in[14];
    const float* Wc2 = (const float*)d_in[15];
    const float* bc2 = (const float*)d_in[16];
    const float* Ws1 = (const float*)d_in[17];
    const float* bs1 = (const float*)d_in[18];
    const float* Ws2 = (const float*)d_in[19];
    const float* bs2 = (const float*)d_in[20];
    float* out = (float*)d_out;

    cudaFuncSetAttribute(k_rows_mma, cudaFuncAttributeMaxDynamicSharedMemorySize, SMEM_SZ);

    k_prep<<<4, 256>>>(W1, W2, Wa1);
    k_rows_mma<<<MROWS / 128, 256, SMEM_SZ>>>(x, b1, g1, be1, b2, g2, be2, ba1, ba2, Wa2);
    k_wsum<<<NBAG * NCHUNK3, 256>>>();
    k_final<<<NBAG, 128>>>(Wc1, bc1, Wc2, bc2, Ws1, bs1, Ws2, bs2, out);
}

// round 15
// speedup vs baseline: 1.0250x; 1.0250x over previous
#include <cuda_runtime.h>
#include <cuda_bf16.h>
#include <cuda_fp16.h>
#include <math.h>
#include <stdint.h>

// ---------------- problem constants ----------------
#define MROWS   400000
#define NBAG    8
#define NPER    50000
#define DIN     256
#define HDIM    128
#define INV_TAU (1.0f/0.3f)
#define LN_EPS  1e-5f
#define CHUNK   256
#define NCHUNK3 196              // ceil(50000/256)

// ---------------- scratch globals ----------------
__device__ __half g_h2h[(size_t)MROWS * HDIM];          // 102.4 MB (fp16)
__device__ float g_scores[MROWS];
__device__ uint32_t g_bagmaxi[NBAG];                    // order-preserving uint max
__device__ float g_pvec[NBAG * NCHUNK3 * HDIM];
__device__ float g_pZ[NBAG * NCHUNK3];
// fp16 hi/lo weights, dense [n][k]: [W1half0, W1half1, W2, Wa1] x [hi 32KB | lo 32KB]
__device__ __align__(16) unsigned char g_wsw[4 * 65536];

// ---------------- smem layout (bytes), single CTA = 73808 -> 2 CTAs/SM ----------------
#define B_HI_OFF  0              // weight buffer hi [128][136] fp16
#define BLO       34816          // hi -> lo offset
#define BIAS_OFF  69632          // 1025 floats (4100 B)
#define RED2_OFF  73744          // 16 floats: per-warp [lo,hi] score maxima
#define SMEM_SZ   73808

__device__ __forceinline__ uint32_t smem_to_u32(const void* p) {
    uint32_t a;
    asm("{ .reg .u64 t; cvta.to.shared.u64 t, %1; cvt.u32.u64 %0, t; }" : "=r"(a) : "l"(p));
    return a;
}

#define LDM4(r, addr) \
    asm volatile("ldmatrix.sync.aligned.m8n8.x4.shared.b16 {%0,%1,%2,%3}, [%4];" \
        : "=r"((r)[0]), "=r"((r)[1]), "=r"((r)[2]), "=r"((r)[3]) : "r"(addr))

#define MMA16816(c, a, b0, b1) \
    asm volatile("mma.sync.aligned.m16n8k16.row.col.f32.f16.f16.f32 " \
        "{%0,%1,%2,%3}, {%4,%5,%6,%7}, {%8,%9}, {%0,%1,%2,%3};" \
        : "+f"((c)[0]), "+f"((c)[1]), "+f"((c)[2]), "+f"((c)[3]) \
        : "r"((a)[0]), "r"((a)[1]), "r"((a)[2]), "r"((a)[3]), "r"(b0), "r"(b1))

#define CP_ASYNC16(saddr, gptr) \
    asm volatile("cp.async.ca.shared.global [%0], [%1], 16;" :: "r"(saddr), "l"(gptr) : "memory")
#define CP_COMMIT() asm volatile("cp.async.commit_group;" ::: "memory")
#define CP_WAIT(n)  asm volatile("cp.async.wait_group %0;" :: "n"(n) : "memory")

__device__ __forceinline__ float fast_tanh(float x) {
    float e = __expf(2.0f * x);
    return 1.0f - __fdividef(2.0f, e + 1.0f);
}
__device__ __forceinline__ uint32_t pack_h2(float a, float b) {
    __half2 h = __floats2half2_rn(a, b);
    return *(uint32_t*)&h;
}
// order-preserving float->uint key (monotonic): max over keys == max over floats
__device__ __forceinline__ uint32_t fkey(float f) {
    uint32_t u = __float_as_uint(f);
    return (u & 0x80000000u) ? ~u : (u | 0x80000000u);
}
__device__ __forceinline__ float funkey(uint32_t k) {
    return (k & 0x80000000u) ? __uint_as_float(k & 0x7FFFFFFFu) : __uint_as_float(~k);
}

// ---------------- weight prep: fp32 -> dense fp16 hi/lo [n][k]; reset bagmax ----------------
__global__ void k_prep(const float* __restrict__ W1, const float* __restrict__ W2,
                       const float* __restrict__ Wa1)
{
    if (blockIdx.x == 0 && threadIdx.x < NBAG) g_bagmaxi[threadIdx.x] = 0u;
    int mat = blockIdx.x;
    const float* W; int koff;
    if (mat == 0)      { W = W1;  koff = 0;   }
    else if (mat == 1) { W = W1;  koff = 128; }
    else if (mat == 2) { W = W2;  koff = 0;   }
    else               { W = Wa1; koff = 0;   }
    __half* dh = (__half*)(g_wsw + (size_t)mat * 65536);
    __half* dl = dh + 16384;
    for (int idx = threadIdx.x; idx < 16384; idx += blockDim.x) {
        int n = idx >> 7, k = idx & 127;
        float w = W[(size_t)(koff + k) * 128 + n];   // B[n][k] = W[k][n]
        __half h = __float2half_rn(w);
        __half l = __float2half_rn(w - __half2float(h));
        dh[n * 128 + k] = h;
        dl[n * 128 + k] = l;
    }
}

// ---------------- staging ----------------
__device__ __forceinline__ void stage_w_async(uint32_t smb, int mat, int tid) {
    const unsigned char* src = g_wsw + (size_t)mat * 65536;
    unsigned long long gbase = (unsigned long long)__cvta_generic_to_global((void*)src);
#pragma unroll
    for (int i = 0; i < 8; i++) {
        int idx = tid + i * 256;
        int r = idx >> 4, q = idx & 15;
        uint32_t soff = (uint32_t)(r * 136 + q * 8) * 2u;
        unsigned long long goff = (unsigned long long)(r * 128 + q * 8) * 2ull;
        CP_ASYNC16(smb + B_HI_OFF + soff,       gbase + goff);
        CP_ASYNC16(smb + B_HI_OFF + BLO + soff, gbase + 32768ull + goff);
    }
}
__device__ __forceinline__ void stage_w_async_hi(uint32_t smb, int mat, int tid) {
    const unsigned char* src = g_wsw + (size_t)mat * 65536;
    unsigned long long gbase = (unsigned long long)__cvta_generic_to_global((void*)src);
#pragma unroll
    for (int i = 0; i < 8; i++) {
        int idx = tid + i * 256;
        int r = idx >> 4, q = idx & 15;
        uint32_t soff = (uint32_t)(r * 136 + q * 8) * 2u;
        unsigned long long goff = (unsigned long long)(r * 128 + q * 8) * 2ull;
        CP_ASYNC16(smb + B_HI_OFF + soff, gbase + goff);
    }
}

// ---------------- inners (explicit B prefetch) ----------------
// 2-pass (B hi + lo) — phase 2 only
__device__ __forceinline__ void mma_inner(uint32_t smb, uint32_t bRow, uint32_t bK0, int ks,
                                          const uint32_t* a, float (*acc)[4]) {
    uint32_t base = smb + B_HI_OFF + (bRow + bK0 + (uint32_t)ks * 16u) * 2u;
    uint32_t bh[4], bl[4];
    LDM4(bh, base);
    LDM4(bl, base + BLO);
#pragma unroll
    for (int nt2 = 0; nt2 < 8; nt2++) {
        uint32_t nh[4], nl[4];
        if (nt2 < 7) {
            uint32_t naddr = base + (uint32_t)(nt2 + 1) * (16u * 136u * 2u);
            LDM4(nh, naddr);
            LDM4(nl, naddr + BLO);
        }
        MMA16816(acc[2 * nt2],     a, bh[0], bh[1]);
        MMA16816(acc[2 * nt2 + 1], a, bh[2], bh[3]);
        MMA16816(acc[2 * nt2],     a, bl[0], bl[1]);
        MMA16816(acc[2 * nt2 + 1], a, bl[2], bl[3]);
        if (nt2 < 7) {
#pragma unroll
            for (int j = 0; j < 4; j++) { bh[j] = nh[j]; bl[j] = nl[j]; }
        }
    }
}
// single-pass (B hi only) — phases 1, 3
__device__ __forceinline__ void mma_inner_hi(uint32_t smb, uint32_t bRow, uint32_t bK0, int ks,
                                             const uint32_t* a, float (*acc)[4]) {
    uint32_t base = smb + B_HI_OFF + (bRow + bK0 + (uint32_t)ks * 16u) * 2u;
    uint32_t bh[4];
    LDM4(bh, base);
#pragma unroll
    for (int nt2 = 0; nt2 < 8; nt2++) {
        uint32_t nh[4];
        if (nt2 < 7) {
            LDM4(nh, base + (uint32_t)(nt2 + 1) * (16u * 136u * 2u));
        }
        MMA16816(acc[2 * nt2],     a, bh[0], bh[1]);
        MMA16816(acc[2 * nt2 + 1], a, bh[2], bh[3]);
        if (nt2 < 7) {
#pragma unroll
            for (int j = 0; j < 4; j++) bh[j] = nh[j];
        }
    }
}

// phase-1 block: A straight from gmem x, depth-2 software pipeline
__device__ __forceinline__ void mma_block_g(uint32_t smb, const float* __restrict__ x,
                                            size_t rowTile, int hh, int w, int L,
                                            float (*acc)[4]) {
    const int g = L >> 2, t = L & 3;
    const float* p0 = x + (rowTile + (size_t)(w * 16 + g)) * DIN + hh * 128 + 2 * t;
    const float* p1 = p0 + 8 * DIN;
    const int g3 = L >> 3, rr = L & 7;
    const uint32_t bRow = (uint32_t)((g3 >> 1) * 8 + rr) * 136u;
    const uint32_t bK0  = 8u * (uint32_t)(g3 & 1);

    float2 buf[2][4];
#pragma unroll
    for (int s = 0; s < 2; s++) {
        buf[s][0] = *(const float2*)(p0 + s * 16);
        buf[s][1] = *(const float2*)(p1 + s * 16);
        buf[s][2] = *(const float2*)(p0 + s * 16 + 8);
        buf[s][3] = *(const float2*)(p1 + s * 16 + 8);
    }
#pragma unroll
    for (int ks = 0; ks < 8; ks++) {
        float2 n0, n1, n2, n3;
        if (ks < 6) {
            n0 = *(const float2*)(p0 + (ks + 2) * 16);
            n1 = *(const float2*)(p1 + (ks + 2) * 16);
            n2 = *(const float2*)(p0 + (ks + 2) * 16 + 8);
            n3 = *(const float2*)(p1 + (ks + 2) * 16 + 8);
        }
        const int s = ks & 1;
        uint32_t a[4];
        a[0] = pack_h2(buf[s][0].x, buf[s][0].y);
        a[1] = pack_h2(buf[s][1].x, buf[s][1].y);
        a[2] = pack_h2(buf[s][2].x, buf[s][2].y);
        a[3] = pack_h2(buf[s][3].x, buf[s][3].y);
        mma_inner_hi(smb, bRow, bK0, ks, a, acc);
        if (ks < 6) { buf[s][0] = n0; buf[s][1] = n1; buf[s][2] = n2; buf[s][3] = n3; }
    }
}

// phase-2 block: A from regs, 2-pass B
__device__ __forceinline__ void mma_block_r(uint32_t smb, const uint32_t* afh, int L,
                                            float (*acc)[4]) {
    const int g3 = L >> 3, rr = L & 7;
    const uint32_t bRow = (uint32_t)((g3 >> 1) * 8 + rr) * 136u;
    const uint32_t bK0  = 8u * (uint32_t)(g3 & 1);
#pragma unroll 2
    for (int ks = 0; ks < 8; ks++)
        mma_inner(smb, bRow, bK0, ks, afh + ks * 4, acc);
}
// phase-3 block: A from regs, single-pass B
__device__ __forceinline__ void mma_block_r1(uint32_t smb, const uint32_t* afh, int L,
                                             float (*acc)[4]) {
    const int g3 = L >> 3, rr = L & 7;
    const uint32_t bRow = (uint32_t)((g3 >> 1) * 8 + rr) * 136u;
    const uint32_t bK0  = 8u * (uint32_t)(g3 & 1);
#pragma unroll 2
    for (int ks = 0; ks < 8; ks++)
        mma_inner_hi(smb, bRow, bK0, ks, afh + ks * 4, acc);
}

__device__ __forceinline__ void repack_A(float (*acc)[4], uint32_t* afh) {
#pragma unroll
    for (int j = 0; j < 8; j++) {
        afh[4 * j]     = pack_h2(acc[2 * j][0],     acc[2 * j][1]);
        afh[4 * j + 1] = pack_h2(acc[2 * j][2],     acc[2 * j][3]);
        afh[4 * j + 2] = pack_h2(acc[2 * j + 1][0], acc[2 * j + 1][1]);
        afh[4 * j + 3] = pack_h2(acc[2 * j + 1][2], acc[2 * j + 1][3]);
    }
}

// ---------------- LN + ReLU epilogue (full row per warp, shuffle-only) ----------------
__device__ __forceinline__ void ln_relu(float (*acc)[4], const float* bias, int boff, int L) {
    const int q2 = 2 * (L & 3);
    float s0 = 0.f, s1 = 0.f;
#pragma unroll
    for (int nt = 0; nt < 16; nt++) {
        int c = nt * 8 + q2;
        float b0 = bias[boff + c], b1v = bias[boff + c + 1];
        acc[nt][0] += b0; acc[nt][1] += b1v; acc[nt][2] += b0; acc[nt][3] += b1v;
        s0 += acc[nt][0] + acc[nt][1];
        s1 += acc[nt][2] + acc[nt][3];
    }
    s0 += __shfl_xor_sync(0xffffffffu, s0, 1); s0 += __shfl_xor_sync(0xffffffffu, s0, 2);
    s1 += __shfl_xor_sync(0xffffffffu, s1, 1); s1 += __shfl_xor_sync(0xffffffffu, s1, 2);
    float mu0 = s0 * 0.0078125f, mu1 = s1 * 0.0078125f;
    float v0 = 0.f, v1 = 0.f;
#pragma unroll
    for (int nt = 0; nt < 16; nt++) {
        float d;
        d = acc[nt][0] - mu0; v0 = fmaf(d, d, v0);
        d = acc[nt][1] - mu0; v0 = fmaf(d, d, v0);
        d = acc[nt][2] - mu1; v1 = fmaf(d, d, v1);
        d = acc[nt][3] - mu1; v1 = fmaf(d, d, v1);
    }
    v0 += __shfl_xor_sync(0xffffffffu, v0, 1); v0 += __shfl_xor_sync(0xffffffffu, v0, 2);
    v1 += __shfl_xor_sync(0xffffffffu, v1, 1); v1 += __shfl_xor_sync(0xffffffffu, v1, 2);
    float i0 = rsqrtf(fmaf(v0, 0.0078125f, LN_EPS));
    float i1 = rsqrtf(fmaf(v1, 0.0078125f, LN_EPS));
#pragma unroll
    for (int nt = 0; nt < 16; nt++) {
        int c = nt * 8 + q2;
        float g0 = bias[boff + 128 + c], g1v = bias[boff + 128 + c + 1];
        float e0 = bias[boff + 256 + c], e1v = bias[boff + 256 + c + 1];
        acc[nt][0] = fmaxf(fmaf((acc[nt][0] - mu0) * i0, g0, e0), 0.f);
        acc[nt][1] = fmaxf(fmaf((acc[nt][1] - mu0) * i0, g1v, e1v), 0.f);
        acc[nt][2] = fmaxf(fmaf((acc[nt][2] - mu1) * i1, g0, e0), 0.f);
        acc[nt][3] = fmaxf(fmaf((acc[nt][3] - mu1) * i1, g1v, e1v), 0.f);
    }
}

// ---------------- fused row kernel (2 CTAs/SM) ----------------
__global__ void __launch_bounds__(256, 2)
k_rows_mma(const float* __restrict__ x,
           const float* __restrict__ b1, const float* __restrict__ g1, const float* __restrict__ be1,
           const float* __restrict__ b2, const float* __restrict__ g2, const float* __restrict__ be2,
           const float* __restrict__ ba1, const float* __restrict__ ba2, const float* __restrict__ Wa2)
{
    extern __shared__ char sm[];
    const uint32_t smb = smem_to_u32(sm);
    const int tid = threadIdx.x;
    const int w = tid >> 5, L = tid & 31;
    const size_t rowTile = (size_t)blockIdx.x * 128;
    float* bias = (float*)(sm + BIAS_OFF);
    float* red2 = (float*)(sm + RED2_OFF);

    stage_w_async_hi(smb, 0, tid); CP_COMMIT();   // W1 half0 (hi only)

    if (tid < 128) {
        bias[tid]       = b1[tid];  bias[128 + tid] = g1[tid];  bias[256 + tid] = be1[tid];
        bias[384 + tid] = b2[tid];  bias[512 + tid] = g2[tid];  bias[640 + tid] = be2[tid];
        bias[768 + tid] = ba1[tid]; bias[896 + tid] = Wa2[tid];
    }
    if (tid == 0) bias[1024] = ba2[0];

    float acc[16][4];
#pragma unroll
    for (int nt = 0; nt < 16; nt++)
#pragma unroll
        for (int j = 0; j < 4; j++) acc[nt][j] = 0.f;

    // ===== PHASE 1: x @ W1 (hi-only; A from gmem, depth-2 pipeline) =====
    CP_WAIT(0);
    __syncthreads();
    mma_block_g(smb, x, rowTile, 0, w, L, acc);
    __syncthreads();
    stage_w_async_hi(smb, 1, tid); CP_COMMIT();   // W1 half1 (hi only)
    CP_WAIT(0);
    __syncthreads();
    mma_block_g(smb, x, rowTile, 1, w, L, acc);
    __syncthreads();
    stage_w_async(smb, 2, tid); CP_COMMIT();      // W2 hi+lo (overlaps LN1)

    uint32_t afh[32];
    ln_relu(acc, bias, 0, L);
    repack_A(acc, afh);
    CP_WAIT(0);
    __syncthreads();

    // ===== PHASE 2: h1 @ W2 (2-pass: precision-critical, feeds bag average) =====
#pragma unroll
    for (int nt = 0; nt < 16; nt++)
#pragma unroll
        for (int j = 0; j < 4; j++) acc[nt][j] = 0.f;
    mma_block_r(smb, afh, L, acc);
    __syncthreads();
    stage_w_async_hi(smb, 3, tid); CP_COMMIT();   // Wa1 hi (overlaps LN2 + h2 store)

    ln_relu(acc, bias, 384, L);
    // h2 -> gmem fp16, direct from fragments
    {
        const int r0 = w * 16 + (L >> 2), r1 = r0 + 8;
        const int q2 = 2 * (L & 3);
        __half* h0p = g_h2h + (rowTile + r0) * HDIM;
        __half* h1p = g_h2h + (rowTile + r1) * HDIM;
#pragma unroll
        for (int nt = 0; nt < 16; nt++) {
            int c = nt * 8 + q2;
            *(uint32_t*)(h0p + c) = pack_h2(acc[nt][0], acc[nt][1]);
            *(uint32_t*)(h1p + c) = pack_h2(acc[nt][2], acc[nt][3]);
        }
    }
    repack_A(acc, afh);
    CP_WAIT(0);
    __syncthreads();

    // ===== PHASE 3: h2 @ Wa1 (hi-only) -> tanh -> dot Wa2 -> scores + fused bag max =====
#pragma unroll
    for (int nt = 0; nt < 16; nt++)
#pragma unroll
        for (int j = 0; j < 4; j++) acc[nt][j] = 0.f;
    mma_block_r1(smb, afh, L, acc);

    {
        const int r0 = w * 16 + (L >> 2), r1 = r0 + 8;
        const int q2 = 2 * (L & 3);
        float p0 = 0.f, p1 = 0.f;
#pragma unroll
        for (int nt = 0; nt < 16; nt++) {
            int c = nt * 8 + q2;
            float wa0 = bias[896 + c], wa1v = bias[896 + c + 1];
            float bb0 = bias[768 + c], bb1 = bias[768 + c + 1];
            p0 = fmaf(fast_tanh(acc[nt][0] + bb0), wa0, p0);
            p0 = fmaf(fast_tanh(acc[nt][1] + bb1), wa1v, p0);
            p1 = fmaf(fast_tanh(acc[nt][2] + bb0), wa0, p1);
            p1 = fmaf(fast_tanh(acc[nt][3] + bb1), wa1v, p1);
        }
        p0 += __shfl_xor_sync(0xffffffffu, p0, 1); p0 += __shfl_xor_sync(0xffffffffu, p0, 2);
        p1 += __shfl_xor_sync(0xffffffffu, p1, 1); p1 += __shfl_xor_sync(0xffffffffu, p1, 2);
        const float bb = bias[1024];
        const float s0v = p0 + bb, s1v = p1 + bb;
        if ((L & 3) == 0) {
            g_scores[rowTile + r0] = s0v;
            g_scores[rowTile + r1] = s1v;
        }
        // fused per-bag max (deterministic: pure max reduction + atomicMax on keys)
        const int bagB = (int)((rowTile + 127) / NPER);
        const size_t boundary = (size_t)bagB * NPER;   // rows >= boundary belong to bagB
        float mlo = -3.4e38f, mhi = -3.4e38f;
        if (rowTile + r0 >= boundary) mhi = fmaxf(mhi, s0v); else mlo = fmaxf(mlo, s0v);
        if (rowTile + r1 >= boundary) mhi = fmaxf(mhi, s1v); else mlo = fmaxf(mlo, s1v);
#pragma unroll
        for (int off = 16; off; off >>= 1) {
            mlo = fmaxf(mlo, __shfl_xor_sync(0xffffffffu, mlo, off));
            mhi = fmaxf(mhi, __shfl_xor_sync(0xffffffffu, mhi, off));
        }
        if (L == 0) { red2[w * 2] = mlo; red2[w * 2 + 1] = mhi; }
        __syncthreads();
        if (tid == 0) {
            float Mlo = -3.4e38f, Mhi = -3.4e38f;
#pragma unroll
            for (int q = 0; q < 8; q++) {
                Mlo = fmaxf(Mlo, red2[q * 2]);
                Mhi = fmaxf(Mhi, red2[q * 2 + 1]);
            }
            const int bagA = (int)(rowTile / NPER);
            if (bagA != bagB) {
                atomicMax(&g_bagmaxi[bagA], fkey(Mlo));
                atomicMax(&g_bagmaxi[bagB], fkey(Mhi));
            } else {
                atomicMax(&g_bagmaxi[bagA], fkey(fmaxf(Mlo, Mhi)));
            }
        }
    }
}

// ---------------- weighted partial sums (chunks of 256 rows, fp16 h2, MLP 8) ----------------
__global__ __launch_bounds__(256)
void k_wsum()
{
    const int b = blockIdx.x / NCHUNK3;
    const int c = blockIdx.x % NCHUNK3;
    const int tid = threadIdx.x;
    const int base = c * CHUNK;
    const int cnt = min(CHUNK, NPER - base);
    __shared__ float wrow[CHUNK];
    __shared__ float2 sred[256];

    const float bm = funkey(g_bagmaxi[b]);
    wrow[tid] = (tid < cnt) ? expf((g_scores[(size_t)b * NPER + base + tid] - bm) * INV_TAU) : 0.f;
    __syncthreads();

    const int c2 = tid & 63;
    const int rg = tid >> 6;
    const uint32_t* hp = (const uint32_t*)(g_h2h + ((size_t)b * NPER + base) * HDIM) + c2;

    float2 a0 = {0.f,0.f}, a1 = {0.f,0.f}, a2 = {0.f,0.f}, a3 = {0.f,0.f};
    int n = rg;
    for (; n + 28 < cnt; n += 32) {
        uint32_t u[8];
#pragma unroll
        for (int j = 0; j < 8; j++) u[j] = hp[(size_t)(n + 4 * j) * 64];
#pragma unroll
        for (int j = 0; j < 8; j += 4) {
            float2 f0 = __half22float2(*(const __half2*)&u[j]);
            float2 f1 = __half22float2(*(const __half2*)&u[j + 1]);
            float2 f2 = __half22float2(*(const __half2*)&u[j + 2]);
            float2 f3 = __half22float2(*(const __half2*)&u[j + 3]);
            float w0 = wrow[n + 4 * j], w1 = wrow[n + 4 * j + 4];
            float w2 = wrow[n + 4 * j + 8], w3 = wrow[n + 4 * j + 12];
            a0.x = fmaf(w0, f0.x, a0.x); a0.y = fmaf(w0, f0.y, a0.y);
            a1.x = fmaf(w1, f1.x, a1.x); a1.y = fmaf(w1, f1.y, a1.y);
            a2.x = fmaf(w2, f2.x, a2.x); a2.y = fmaf(w2, f2.y, a2.y);
            a3.x = fmaf(w3, f3.x, a3.x); a3.y = fmaf(w3, f3.y, a3.y);
        }
    }
    for (; n < cnt; n += 4) {
        uint32_t u = hp[(size_t)n * 64];
        float2 f = __half22float2(*(const __half2*)&u);
        float wv = wrow[n];
        a0.x = fmaf(wv, f.x, a0.x); a0.y = fmaf(wv, f.y, a0.y);
    }
    float2 at;
    at.x = (a0.x + a1.x) + (a2.x + a3.x);
    at.y = (a0.y + a1.y) + (a2.y + a3.y);
    sred[tid] = at;
    __syncthreads();
    if (tid < 64) {
        float2 t0 = sred[tid], t1 = sred[tid + 64], t2 = sred[tid + 128], t3 = sred[tid + 192];
        float* pv = g_pvec + ((size_t)b * NCHUNK3 + c) * HDIM;
        pv[2 * tid]     = (t0.x + t1.x) + (t2.x + t3.x);
        pv[2 * tid + 1] = (t0.y + t1.y) + (t2.y + t3.y);
    }

    __syncthreads();
    for (int off = 128; off; off >>= 1) {
        if (tid < off) wrow[tid] += wrow[tid + off];
        __syncthreads();
    }
    if (tid == 0) g_pZ[b * NCHUNK3 + c] = wrow[0];
}

// ---------------- final heads (1024 thr: 8-way parallel chunk reduction) ----------------
__global__ __launch_bounds__(1024)
void k_final(const float* __restrict__ Wc1, const float* __restrict__ bc1,
             const float* __restrict__ Wc2, const float* __restrict__ bc2,
             const float* __restrict__ Ws1, const float* __restrict__ bs1,
             const float* __restrict__ Ws2, const float* __restrict__ bs2,
             float* __restrict__ out)
{
    const int bag = blockIdx.x;
    const int tid = threadIdx.x;
    const int col = tid & 127, grp = tid >> 7;    // 8 groups x 128 cols
    __shared__ float vred[1024];
    __shared__ float zred[256];
    __shared__ float bagn[128];
    __shared__ float hid[128];
    __shared__ float hs[64];

    // pvec reduction: group g sums chunks g, g+8, ... (independent loads, deep MLP)
    float vv = 0.0f;
    for (int c = grp; c < NCHUNK3; c += 8)
        vv += g_pvec[((size_t)bag * NCHUNK3 + c) * HDIM + col];
    vred[tid] = vv;

    // Z reduction with 256 threads in parallel
    if (tid < 256) {
        float zp = 0.0f;
        for (int c = tid; c < NCHUNK3; c += 256)
            zp += g_pZ[bag * NCHUNK3 + c];
        zred[tid] = zp;
    }
    __syncthreads();
    if (tid < 512) vred[tid] += vred[tid + 512];
    if (tid < 128) zred[tid] += zred[tid + 128];
    __syncthreads();
    if (tid < 256) vred[tid] += vred[tid + 256];
    if (tid < 64)  zred[tid] += zred[tid + 64];
    __syncthreads();
    if (tid < 128) vred[tid] += vred[tid + 128];
    if (tid < 32)  zred[tid] += zred[tid + 32];
    __syncthreads();
    if (tid < 16) zred[tid] += zred[tid + 16];
    __syncthreads();
    if (tid < 8) zred[tid] += zred[tid + 8];
    __syncthreads();
    if (tid < 4) zred[tid] += zred[tid + 4];
    __syncthreads();
    if (tid < 2) zred[tid] += zred[tid + 2];
    __syncthreads();
    if (tid == 0) zred[0] += zred[1];
    __syncthreads();
    const float Z = zred[0];
    if (tid < 128) bagn[tid] = vred[tid] / Z;
    __syncthreads();

    if (tid < 128) {
        float h = bc1[tid];
        for (int k = 0; k < 128; k++) h = fmaf(bagn[k], Wc1[k * 128 + tid], h);
        hid[tid] = fmaxf(h, 0.0f);
    }
    if (tid >= 128 && tid < 192) {
        int t = tid - 128;
        float h = bs1[t];
        for (int k = 0; k < 128; k++) h = fmaf(bagn[k], Ws1[k * 64 + t], h);
        hs[t] = fmaxf(h, 0.0f);
    }
    __syncthreads();

    if (tid < 2) {
        float s = bc2[tid];
        for (int j = 0; j < 128; j++) s = fmaf(hid[j], Wc2[j * 2 + tid], s);
        out[bag * 2 + tid] = s;
    }
    if (tid == 2) {
        float r = bs2[0];
        for (int j = 0; j < 64; j++) r = fmaf(hs[j], Ws2[j], r);
        out[16 + bag] = r;
    }
}

extern "C" void kernel_launch(void* const* d_in, const int* in_sizes, int n_in,
                              void* d_out, int out_size)
{
    const float* x   = (const float*)d_in[0];
    const float* W1  = (const float*)d_in[1];
    const float* b1  = (const float*)d_in[2];
    const float* g1  = (const float*)d_in[3];
    const float* be1 = (const float*)d_in[4];
    const float* W2  = (const float*)d_in[5];
    const float* b2  = (const float*)d_in[6];
    const float* g2  = (const float*)d_in[7];
    const float* be2 = (const float*)d_in[8];
    const float* Wa1 = (const float*)d_in[9];
    const float* ba1 = (const float*)d_in[10];
    const float* Wa2 = (const float*)d_in[11];
    const float* ba2 = (const float*)d_in[12];
    const float* Wc1 = (const float*)d_in[13];
    const float* bc1 = (const float*)d_in[14];
    const float* Wc2 = (const float*)d_in[15];
    const float* bc2 = (const float*)d_in[16];
    const float* Ws1 = (const float*)d_in[17];
    const float* bs1 = (const float*)d_in[18];
    const float* Ws2 = (const float*)d_in[19];
    const float* bs2 = (const float*)d_in[20];
    float* out = (float*)d_out;

    cudaFuncSetAttribute(k_rows_mma, cudaFuncAttributeMaxDynamicSharedMemorySize, SMEM_SZ);

    k_prep<<<4, 256>>>(W1, W2, Wa1);
    k_rows_mma<<<MROWS / 128, 256, SMEM_SZ>>>(x, b1, g1, be1, b2, g2, be2, ba1, ba2, Wa2);
    k_wsum<<<NBAG * NCHUNK3, 256>>>();
    k_final<<<NBAG, 1024>>>(Wc1, bc1, Wc2, bc2, Ws1, bs1, Ws2, bs2, out);
}

// round 17
// speedup vs baseline: 1.0453x; 1.0199x over previous
#include <cuda_runtime.h>
#include <cuda_bf16.h>
#include <cuda_fp16.h>
#include <math.h>
#include <stdint.h>

// ---------------- problem constants ----------------
#define MROWS   400000
#define NBAG    8
#define NPER    50000
#define DIN     256
#define HDIM    128
#define INV_TAU (1.0f/0.3f)
#define LN_EPS  1e-5f
#define CHUNK   256
#define NCHUNK3 196              // ceil(50000/256)

// ---------------- scratch globals ----------------
__device__ __half g_h2h[(size_t)MROWS * HDIM];          // 102.4 MB (fp16)
__device__ float g_scores[MROWS];
__device__ uint32_t g_bagmaxi[NBAG];                    // order-preserving uint max
__device__ float g_pvec[NBAG * NCHUNK3 * HDIM];
__device__ float g_pZ[NBAG * NCHUNK3];
// fp16 hi/lo weights, dense [n][k]: [W1half0, W1half1, W2, Wa1] x [hi 32KB | lo 32KB]
__device__ __align__(16) unsigned char g_wsw[4 * 65536];

// ---------------- smem layout (bytes), single CTA = 73808 -> 2 CTAs/SM ----------------
#define B_HI_OFF  0              // weight buffer hi [128][136] fp16
#define BLO       34816          // hi -> lo offset
#define BIAS_OFF  69632          // 1025 floats (4100 B)
#define RED2_OFF  73744          // 16 floats: per-warp [lo,hi] score maxima
#define SMEM_SZ   73808

__device__ __forceinline__ uint32_t smem_to_u32(const void* p) {
    uint32_t a;
    asm("{ .reg .u64 t; cvta.to.shared.u64 t, %1; cvt.u32.u64 %0, t; }" : "=r"(a) : "l"(p));
    return a;
}

#define LDM4(r, addr) \
    asm volatile("ldmatrix.sync.aligned.m8n8.x4.shared.b16 {%0,%1,%2,%3}, [%4];" \
        : "=r"((r)[0]), "=r"((r)[1]), "=r"((r)[2]), "=r"((r)[3]) : "r"(addr))

#define MMA16816(c, a, b0, b1) \
    asm volatile("mma.sync.aligned.m16n8k16.row.col.f32.f16.f16.f32 " \
        "{%0,%1,%2,%3}, {%4,%5,%6,%7}, {%8,%9}, {%0,%1,%2,%3};" \
        : "+f"((c)[0]), "+f"((c)[1]), "+f"((c)[2]), "+f"((c)[3]) \
        : "r"((a)[0]), "r"((a)[1]), "r"((a)[2]), "r"((a)[3]), "r"(b0), "r"(b1))

#define CP_ASYNC16(saddr, gptr) \
    asm volatile("cp.async.ca.shared.global [%0], [%1], 16;" :: "r"(saddr), "l"(gptr) : "memory")
#define CP_COMMIT() asm volatile("cp.async.commit_group;" ::: "memory")
#define CP_WAIT(n)  asm volatile("cp.async.wait_group %0;" :: "n"(n) : "memory")

__device__ __forceinline__ float fast_tanh(float x) {
    float e = __expf(2.0f * x);
    return 1.0f - __fdividef(2.0f, e + 1.0f);
}
__device__ __forceinline__ uint32_t pack_h2(float a, float b) {
    __half2 h = __floats2half2_rn(a, b);
    return *(uint32_t*)&h;
}
// order-preserving float->uint key (monotonic): max over keys == max over floats
__device__ __forceinline__ uint32_t fkey(float f) {
    uint32_t u = __float_as_uint(f);
    return (u & 0x80000000u) ? ~u : (u | 0x80000000u);
}
__device__ __forceinline__ float funkey(uint32_t k) {
    return (k & 0x80000000u) ? __uint_as_float(k & 0x7FFFFFFFu) : __uint_as_float(~k);
}

// ---------------- weight prep: fp32 -> dense fp16 hi/lo [n][k]; reset bagmax ----------------
__global__ void k_prep(const float* __restrict__ W1, const float* __restrict__ W2,
                       const float* __restrict__ Wa1)
{
    if (blockIdx.x == 0 && threadIdx.x < NBAG) g_bagmaxi[threadIdx.x] = 0u;
    int mat = blockIdx.x;
    const float* W; int koff;
    if (mat == 0)      { W = W1;  koff = 0;   }
    else if (mat == 1) { W = W1;  koff = 128; }
    else if (mat == 2) { W = W2;  koff = 0;   }
    else               { W = Wa1; koff = 0;   }
    __half* dh = (__half*)(g_wsw + (size_t)mat * 65536);
    __half* dl = dh + 16384;
    for (int idx = threadIdx.x; idx < 16384; idx += blockDim.x) {
        int n = idx >> 7, k = idx & 127;
        float w = W[(size_t)(koff + k) * 128 + n];   // B[n][k] = W[k][n]
        __half h = __float2half_rn(w);
        __half l = __float2half_rn(w - __half2float(h));
        dh[n * 128 + k] = h;
        dl[n * 128 + k] = l;
    }
}

// ---------------- staging ----------------
__device__ __forceinline__ void stage_w_async(uint32_t smb, int mat, int tid) {
    const unsigned char* src = g_wsw + (size_t)mat * 65536;
    unsigned long long gbase = (unsigned long long)__cvta_generic_to_global((void*)src);
#pragma unroll
    for (int i = 0; i < 8; i++) {
        int idx = tid + i * 256;
        int r = idx >> 4, q = idx & 15;
        uint32_t soff = (uint32_t)(r * 136 + q * 8) * 2u;
        unsigned long long goff = (unsigned long long)(r * 128 + q * 8) * 2ull;
        CP_ASYNC16(smb + B_HI_OFF + soff,       gbase + goff);
        CP_ASYNC16(smb + B_HI_OFF + BLO + soff, gbase + 32768ull + goff);
    }
}
__device__ __forceinline__ void stage_w_async_hi(uint32_t smb, int mat, int tid) {
    const unsigned char* src = g_wsw + (size_t)mat * 65536;
    unsigned long long gbase = (unsigned long long)__cvta_generic_to_global((void*)src);
#pragma unroll
    for (int i = 0; i < 8; i++) {
        int idx = tid + i * 256;
        int r = idx >> 4, q = idx & 15;
        uint32_t soff = (uint32_t)(r * 136 + q * 8) * 2u;
        unsigned long long goff = (unsigned long long)(r * 128 + q * 8) * 2ull;
        CP_ASYNC16(smb + B_HI_OFF + soff, gbase + goff);
    }
}

// ---------------- inners (explicit B prefetch) ----------------
// 2-pass (B hi + lo) — phase 2 only
__device__ __forceinline__ void mma_inner(uint32_t smb, uint32_t bRow, uint32_t bK0, int ks,
                                          const uint32_t* a, float (*acc)[4]) {
    uint32_t base = smb + B_HI_OFF + (bRow + bK0 + (uint32_t)ks * 16u) * 2u;
    uint32_t bh[4], bl[4];
    LDM4(bh, base);
    LDM4(bl, base + BLO);
#pragma unroll
    for (int nt2 = 0; nt2 < 8; nt2++) {
        uint32_t nh[4], nl[4];
        if (nt2 < 7) {
            uint32_t naddr = base + (uint32_t)(nt2 + 1) * (16u * 136u * 2u);
            LDM4(nh, naddr);
            LDM4(nl, naddr + BLO);
        }
        MMA16816(acc[2 * nt2],     a, bh[0], bh[1]);
        MMA16816(acc[2 * nt2 + 1], a, bh[2], bh[3]);
        MMA16816(acc[2 * nt2],     a, bl[0], bl[1]);
        MMA16816(acc[2 * nt2 + 1], a, bl[2], bl[3]);
        if (nt2 < 7) {
#pragma unroll
            for (int j = 0; j < 4; j++) { bh[j] = nh[j]; bl[j] = nl[j]; }
        }
    }
}
// single-pass (B hi only) — phases 1, 3
__device__ __forceinline__ void mma_inner_hi(uint32_t smb, uint32_t bRow, uint32_t bK0, int ks,
                                             const uint32_t* a, float (*acc)[4]) {
    uint32_t base = smb + B_HI_OFF + (bRow + bK0 + (uint32_t)ks * 16u) * 2u;
    uint32_t bh[4];
    LDM4(bh, base);
#pragma unroll
    for (int nt2 = 0; nt2 < 8; nt2++) {
        uint32_t nh[4];
        if (nt2 < 7) {
            LDM4(nh, base + (uint32_t)(nt2 + 1) * (16u * 136u * 2u));
        }
        MMA16816(acc[2 * nt2],     a, bh[0], bh[1]);
        MMA16816(acc[2 * nt2 + 1], a, bh[2], bh[3]);
        if (nt2 < 7) {
#pragma unroll
            for (int j = 0; j < 4; j++) bh[j] = nh[j];
        }
    }
}

// phase-1 block: A straight from gmem x, depth-2 software pipeline
__device__ __forceinline__ void mma_block_g(uint32_t smb, const float* __restrict__ x,
                                            size_t rowTile, int hh, int w, int L,
                                            float (*acc)[4]) {
    const int g = L >> 2, t = L & 3;
    const float* p0 = x + (rowTile + (size_t)(w * 16 + g)) * DIN + hh * 128 + 2 * t;
    const float* p1 = p0 + 8 * DIN;
    const int g3 = L >> 3, rr = L & 7;
    const uint32_t bRow = (uint32_t)((g3 >> 1) * 8 + rr) * 136u;
    const uint32_t bK0  = 8u * (uint32_t)(g3 & 1);

    float2 buf[2][4];
#pragma unroll
    for (int s = 0; s < 2; s++) {
        buf[s][0] = *(const float2*)(p0 + s * 16);
        buf[s][1] = *(const float2*)(p1 + s * 16);
        buf[s][2] = *(const float2*)(p0 + s * 16 + 8);
        buf[s][3] = *(const float2*)(p1 + s * 16 + 8);
    }
#pragma unroll
    for (int ks = 0; ks < 8; ks++) {
        float2 n0, n1, n2, n3;
        if (ks < 6) {
            n0 = *(const float2*)(p0 + (ks + 2) * 16);
            n1 = *(const float2*)(p1 + (ks + 2) * 16);
            n2 = *(const float2*)(p0 + (ks + 2) * 16 + 8);
            n3 = *(const float2*)(p1 + (ks + 2) * 16 + 8);
        }
        const int s = ks & 1;
        uint32_t a[4];
        a[0] = pack_h2(buf[s][0].x, buf[s][0].y);
        a[1] = pack_h2(buf[s][1].x, buf[s][1].y);
        a[2] = pack_h2(buf[s][2].x, buf[s][2].y);
        a[3] = pack_h2(buf[s][3].x, buf[s][3].y);
        mma_inner_hi(smb, bRow, bK0, ks, a, acc);
        if (ks < 6) { buf[s][0] = n0; buf[s][1] = n1; buf[s][2] = n2; buf[s][3] = n3; }
    }
}

// phase-2 block: A from regs, 2-pass B
__device__ __forceinline__ void mma_block_r(uint32_t smb, const uint32_t* afh, int L,
                                            float (*acc)[4]) {
    const int g3 = L >> 3, rr = L & 7;
    const uint32_t bRow = (uint32_t)((g3 >> 1) * 8 + rr) * 136u;
    const uint32_t bK0  = 8u * (uint32_t)(g3 & 1);
#pragma unroll 2
    for (int ks = 0; ks < 8; ks++)
        mma_inner(smb, bRow, bK0, ks, afh + ks * 4, acc);
}
// phase-3 block: A from regs, single-pass B
__device__ __forceinline__ void mma_block_r1(uint32_t smb, const uint32_t* afh, int L,
                                             float (*acc)[4]) {
    const int g3 = L >> 3, rr = L & 7;
    const uint32_t bRow = (uint32_t)((g3 >> 1) * 8 + rr) * 136u;
    const uint32_t bK0  = 8u * (uint32_t)(g3 & 1);
#pragma unroll 2
    for (int ks = 0; ks < 8; ks++)
        mma_inner_hi(smb, bRow, bK0, ks, afh + ks * 4, acc);
}

__device__ __forceinline__ void repack_A(float (*acc)[4], uint32_t* afh) {
#pragma unroll
    for (int j = 0; j < 8; j++) {
        afh[4 * j]     = pack_h2(acc[2 * j][0],     acc[2 * j][1]);
        afh[4 * j + 1] = pack_h2(acc[2 * j][2],     acc[2 * j][3]);
        afh[4 * j + 2] = pack_h2(acc[2 * j + 1][0], acc[2 * j + 1][1]);
        afh[4 * j + 3] = pack_h2(acc[2 * j + 1][2], acc[2 * j + 1][3]);
    }
}

// ---------------- LN + ReLU epilogue (full row per warp, shuffle-only) ----------------
__device__ __forceinline__ void ln_relu(float (*acc)[4], const float* bias, int boff, int L) {
    const int q2 = 2 * (L & 3);
    float s0 = 0.f, s1 = 0.f;
#pragma unroll
    for (int nt = 0; nt < 16; nt++) {
        int c = nt * 8 + q2;
        float b0 = bias[boff + c], b1v = bias[boff + c + 1];
        acc[nt][0] += b0; acc[nt][1] += b1v; acc[nt][2] += b0; acc[nt][3] += b1v;
        s0 += acc[nt][0] + acc[nt][1];
        s1 += acc[nt][2] + acc[nt][3];
    }
    s0 += __shfl_xor_sync(0xffffffffu, s0, 1); s0 += __shfl_xor_sync(0xffffffffu, s0, 2);
    s1 += __shfl_xor_sync(0xffffffffu, s1, 1); s1 += __shfl_xor_sync(0xffffffffu, s1, 2);
    float mu0 = s0 * 0.0078125f, mu1 = s1 * 0.0078125f;
    float v0 = 0.f, v1 = 0.f;
#pragma unroll
    for (int nt = 0; nt < 16; nt++) {
        float d;
        d = acc[nt][0] - mu0; v0 = fmaf(d, d, v0);
        d = acc[nt][1] - mu0; v0 = fmaf(d, d, v0);
        d = acc[nt][2] - mu1; v1 = fmaf(d, d, v1);
        d = acc[nt][3] - mu1; v1 = fmaf(d, d, v1);
    }
    v0 += __shfl_xor_sync(0xffffffffu, v0, 1); v0 += __shfl_xor_sync(0xffffffffu, v0, 2);
    v1 += __shfl_xor_sync(0xffffffffu, v1, 1); v1 += __shfl_xor_sync(0xffffffffu, v1, 2);
    float i0 = rsqrtf(fmaf(v0, 0.0078125f, LN_EPS));
    float i1 = rsqrtf(fmaf(v1, 0.0078125f, LN_EPS));
#pragma unroll
    for (int nt = 0; nt < 16; nt++) {
        int c = nt * 8 + q2;
        float g0 = bias[boff + 128 + c], g1v = bias[boff + 128 + c + 1];
        float e0 = bias[boff + 256 + c], e1v = bias[boff + 256 + c + 1];
        acc[nt][0] = fmaxf(fmaf((acc[nt][0] - mu0) * i0, g0, e0), 0.f);
        acc[nt][1] = fmaxf(fmaf((acc[nt][1] - mu0) * i0, g1v, e1v), 0.f);
        acc[nt][2] = fmaxf(fmaf((acc[nt][2] - mu1) * i1, g0, e0), 0.f);
        acc[nt][3] = fmaxf(fmaf((acc[nt][3] - mu1) * i1, g1v, e1v), 0.f);
    }
}

// ---------------- fused row kernel (2 CTAs/SM) ----------------
__global__ void __launch_bounds__(256, 2)
k_rows_mma(const float* __restrict__ x,
           const float* __restrict__ b1, const float* __restrict__ g1, const float* __restrict__ be1,
           const float* __restrict__ b2, const float* __restrict__ g2, const float* __restrict__ be2,
           const float* __restrict__ ba1, const float* __restrict__ ba2, const float* __restrict__ Wa2)
{
    extern __shared__ char sm[];
    const uint32_t smb = smem_to_u32(sm);
    const int tid = threadIdx.x;
    const int w = tid >> 5, L = tid & 31;
    const size_t rowTile = (size_t)blockIdx.x * 128;
    float* bias = (float*)(sm + BIAS_OFF);
    float* red2 = (float*)(sm + RED2_OFF);

    stage_w_async_hi(smb, 0, tid); CP_COMMIT();   // W1 half0 (hi only)

    if (tid < 128) {
        bias[tid]       = b1[tid];  bias[128 + tid] = g1[tid];  bias[256 + tid] = be1[tid];
        bias[384 + tid] = b2[tid];  bias[512 + tid] = g2[tid];  bias[640 + tid] = be2[tid];
        bias[768 + tid] = ba1[tid]; bias[896 + tid] = Wa2[tid];
    }
    if (tid == 0) bias[1024] = ba2[0];

    float acc[16][4];
#pragma unroll
    for (int nt = 0; nt < 16; nt++)
#pragma unroll
        for (int j = 0; j < 4; j++) acc[nt][j] = 0.f;

    // ===== PHASE 1: x @ W1 (hi-only; A from gmem, depth-2 pipeline) =====
    CP_WAIT(0);
    __syncthreads();
    mma_block_g(smb, x, rowTile, 0, w, L, acc);
    __syncthreads();
    stage_w_async_hi(smb, 1, tid); CP_COMMIT();   // W1 half1 (hi only)
    CP_WAIT(0);
    __syncthreads();
    mma_block_g(smb, x, rowTile, 1, w, L, acc);
    __syncthreads();
    stage_w_async(smb, 2, tid); CP_COMMIT();      // W2 hi+lo (overlaps LN1)

    uint32_t afh[32];
    ln_relu(acc, bias, 0, L);
    repack_A(acc, afh);
    CP_WAIT(0);
    __syncthreads();

    // ===== PHASE 2: h1 @ W2 (2-pass: precision-critical, feeds bag average) =====
#pragma unroll
    for (int nt = 0; nt < 16; nt++)
#pragma unroll
        for (int j = 0; j < 4; j++) acc[nt][j] = 0.f;
    mma_block_r(smb, afh, L, acc);
    __syncthreads();
    stage_w_async_hi(smb, 3, tid); CP_COMMIT();   // Wa1 hi (overlaps LN2 + h2 store)

    ln_relu(acc, bias, 384, L);
    // h2 -> gmem fp16, direct from fragments
    {
        const int r0 = w * 16 + (L >> 2), r1 = r0 + 8;
        const int q2 = 2 * (L & 3);
        __half* h0p = g_h2h + (rowTile + r0) * HDIM;
        __half* h1p = g_h2h + (rowTile + r1) * HDIM;
#pragma unroll
        for (int nt = 0; nt < 16; nt++) {
            int c = nt * 8 + q2;
            *(uint32_t*)(h0p + c) = pack_h2(acc[nt][0], acc[nt][1]);
            *(uint32_t*)(h1p + c) = pack_h2(acc[nt][2], acc[nt][3]);
        }
    }
    repack_A(acc, afh);
    CP_WAIT(0);
    __syncthreads();

    // ===== PHASE 3: h2 @ Wa1 (hi-only) -> tanh -> dot Wa2 -> scores + fused bag max =====
#pragma unroll
    for (int nt = 0; nt < 16; nt++)
#pragma unroll
        for (int j = 0; j < 4; j++) acc[nt][j] = 0.f;
    mma_block_r1(smb, afh, L, acc);

    {
        const int r0 = w * 16 + (L >> 2), r1 = r0 + 8;
        const int q2 = 2 * (L & 3);
        float p0 = 0.f, p1 = 0.f;
#pragma unroll
        for (int nt = 0; nt < 16; nt++) {
            int c = nt * 8 + q2;
            float wa0 = bias[896 + c], wa1v = bias[896 + c + 1];
            float bb0 = bias[768 + c], bb1 = bias[768 + c + 1];
            p0 = fmaf(fast_tanh(acc[nt][0] + bb0), wa0, p0);
            p0 = fmaf(fast_tanh(acc[nt][1] + bb1), wa1v, p0);
            p1 = fmaf(fast_tanh(acc[nt][2] + bb0), wa0, p1);
            p1 = fmaf(fast_tanh(acc[nt][3] + bb1), wa1v, p1);
        }
        p0 += __shfl_xor_sync(0xffffffffu, p0, 1); p0 += __shfl_xor_sync(0xffffffffu, p0, 2);
        p1 += __shfl_xor_sync(0xffffffffu, p1, 1); p1 += __shfl_xor_sync(0xffffffffu, p1, 2);
        const float bb = bias[1024];
        const float s0v = p0 + bb, s1v = p1 + bb;
        if ((L & 3) == 0) {
            g_scores[rowTile + r0] = s0v;
            g_scores[rowTile + r1] = s1v;
        }
        // fused per-bag max (deterministic: pure max reduction + atomicMax on keys)
        const int bagB = (int)((rowTile + 127) / NPER);
        const size_t boundary = (size_t)bagB * NPER;   // rows >= boundary belong to bagB
        float mlo = -3.4e38f, mhi = -3.4e38f;
        if (rowTile + r0 >= boundary) mhi = fmaxf(mhi, s0v); else mlo = fmaxf(mlo, s0v);
        if (rowTile + r1 >= boundary) mhi = fmaxf(mhi, s1v); else mlo = fmaxf(mlo, s1v);
#pragma unroll
        for (int off = 16; off; off >>= 1) {
            mlo = fmaxf(mlo, __shfl_xor_sync(0xffffffffu, mlo, off));
            mhi = fmaxf(mhi, __shfl_xor_sync(0xffffffffu, mhi, off));
        }
        if (L == 0) { red2[w * 2] = mlo; red2[w * 2 + 1] = mhi; }
        __syncthreads();
        if (tid == 0) {
            float Mlo = -3.4e38f, Mhi = -3.4e38f;
#pragma unroll
            for (int q = 0; q < 8; q++) {
                Mlo = fmaxf(Mlo, red2[q * 2]);
                Mhi = fmaxf(Mhi, red2[q * 2 + 1]);
            }
            const int bagA = (int)(rowTile / NPER);
            if (bagA != bagB) {
                atomicMax(&g_bagmaxi[bagA], fkey(Mlo));
                atomicMax(&g_bagmaxi[bagB], fkey(Mhi));
            } else {
                atomicMax(&g_bagmaxi[bagA], fkey(fmaxf(Mlo, Mhi)));
            }
        }
    }
}

// ---------------- weighted partial sums (chunks of 256 rows, fp16 h2, MLP 8) ----------------
__global__ __launch_bounds__(256)
void k_wsum()
{
    const int b = blockIdx.x / NCHUNK3;
    const int c = blockIdx.x % NCHUNK3;
    const int tid = threadIdx.x;
    const int base = c * CHUNK;
    const int cnt = min(CHUNK, NPER - base);
    __shared__ float wrow[CHUNK];
    __shared__ float2 sred[256];

    const float bm = funkey(g_bagmaxi[b]);
    wrow[tid] = (tid < cnt) ? expf((g_scores[(size_t)b * NPER + base + tid] - bm) * INV_TAU) : 0.f;
    __syncthreads();

    const int c2 = tid & 63;
    const int rg = tid >> 6;
    const uint32_t* hp = (const uint32_t*)(g_h2h + ((size_t)b * NPER + base) * HDIM) + c2;

    float2 a0 = {0.f,0.f}, a1 = {0.f,0.f}, a2 = {0.f,0.f}, a3 = {0.f,0.f};
    int n = rg;
    for (; n + 28 < cnt; n += 32) {
        uint32_t u[8];
#pragma unroll
        for (int j = 0; j < 8; j++) u[j] = hp[(size_t)(n + 4 * j) * 64];
#pragma unroll
        for (int j = 0; j < 8; j += 4) {
            float2 f0 = __half22float2(*(const __half2*)&u[j]);
            float2 f1 = __half22float2(*(const __half2*)&u[j + 1]);
            float2 f2 = __half22float2(*(const __half2*)&u[j + 2]);
            float2 f3 = __half22float2(*(const __half2*)&u[j + 3]);
            float w0 = wrow[n + 4 * j], w1 = wrow[n + 4 * j + 4];
            float w2 = wrow[n + 4 * j + 8], w3 = wrow[n + 4 * j + 12];
            a0.x = fmaf(w0, f0.x, a0.x); a0.y = fmaf(w0, f0.y, a0.y);
            a1.x = fmaf(w1, f1.x, a1.x); a1.y = fmaf(w1, f1.y, a1.y);
            a2.x = fmaf(w2, f2.x, a2.x); a2.y = fmaf(w2, f2.y, a2.y);
            a3.x = fmaf(w3, f3.x, a3.x); a3.y = fmaf(w3, f3.y, a3.y);
        }
    }
    for (; n < cnt; n += 4) {
        uint32_t u = hp[(size_t)n * 64];
        float2 f = __half22float2(*(const __half2*)&u);
        float wv = wrow[n];
        a0.x = fmaf(wv, f.x, a0.x); a0.y = fmaf(wv, f.y, a0.y);
    }
    float2 at;
    at.x = (a0.x + a1.x) + (a2.x + a3.x);
    at.y = (a0.y + a1.y) + (a2.y + a3.y);
    sred[tid] = at;
    __syncthreads();
    if (tid < 64) {
        float2 t0 = sred[tid], t1 = sred[tid + 64], t2 = sred[tid + 128], t3 = sred[tid + 192];
        float* pv = g_pvec + ((size_t)b * NCHUNK3 + c) * HDIM;
        pv[2 * tid]     = (t0.x + t1.x) + (t2.x + t3.x);
        pv[2 * tid + 1] = (t0.y + t1.y) + (t2.y + t3.y);
    }

    // Z: 2 barrier levels + warp shuffle (fixed tree, deterministic)
    __syncthreads();
    if (tid < 128) wrow[tid] += wrow[tid + 128];
    __syncthreads();
    if (tid < 64) wrow[tid] += wrow[tid + 64];
    __syncthreads();
    if (tid < 32) {
        float z = wrow[tid] + wrow[tid + 32];
#pragma unroll
        for (int off = 16; off; off >>= 1) z += __shfl_xor_sync(0xffffffffu, z, off);
        if (tid == 0) g_pZ[b * NCHUNK3 + c] = z;
    }
}

// ---------------- final heads (1024 thr, k-parallel head MLP) ----------------
__global__ __launch_bounds__(1024)
void k_final(const float* __restrict__ Wc1, const float* __restrict__ bc1,
             const float* __restrict__ Wc2, const float* __restrict__ bc2,
             const float* __restrict__ Ws1, const float* __restrict__ bs1,
             const float* __restrict__ Ws2, const float* __restrict__ bs2,
             float* __restrict__ out)
{
    const int bag = blockIdx.x;
    const int tid = threadIdx.x;
    const int col = tid & 127, grp = tid >> 7;    // 8 groups x 128 cols
    __shared__ float vred[1024];
    __shared__ float zred[256];
    __shared__ float bagn[128];
    __shared__ float hidp[1024];                  // 8 x 128 partials
    __shared__ float hsp[512];                    // 8 x 64 partials
    __shared__ float hid[128];
    __shared__ float hs[64];

    // pvec reduction: group g sums chunks g, g+8, ...
    float vv = 0.0f;
    for (int c = grp; c < NCHUNK3; c += 8)
        vv += g_pvec[((size_t)bag * NCHUNK3 + c) * HDIM + col];
    vred[tid] = vv;

    // Z reduction with 256 threads
    if (tid < 256) {
        float zp = 0.0f;
        for (int c = tid; c < NCHUNK3; c += 256)
            zp += g_pZ[bag * NCHUNK3 + c];
        zred[tid] = zp;
    }
    __syncthreads();
    if (tid < 512) vred[tid] += vred[tid + 512];
    if (tid < 128) zred[tid] += zred[tid + 128];
    __syncthreads();
    if (tid < 256) vred[tid] += vred[tid + 256];
    if (tid < 64)  zred[tid] += zred[tid + 64];
    __syncthreads();
    if (tid < 128) vred[tid] += vred[tid + 128];
    if (tid < 32) {
        float z = zred[tid] + zred[tid + 32];
#pragma unroll
        for (int off = 16; off; off >>= 1) z += __shfl_xor_sync(0xffffffffu, z, off);
        if (tid == 0) zred[0] = z;
    }
    __syncthreads();
    const float Z = zred[0];
    if (tid < 128) bagn[tid] = vred[tid] / Z;
    __syncthreads();

    // head MLP, k-parallel: group g covers k in [g*16, g*16+16)
    {
        const int k0 = grp * 16;
        float hp_ = 0.f;
#pragma unroll
        for (int k = 0; k < 16; k++)
            hp_ = fmaf(bagn[k0 + k], Wc1[(k0 + k) * 128 + col], hp_);
        hidp[grp * 128 + col] = hp_;
        if (col < 64) {
            float hr_ = 0.f;
#pragma unroll
            for (int k = 0; k < 16; k++)
                hr_ = fmaf(bagn[k0 + k], Ws1[(k0 + k) * 64 + col], hr_);
            hsp[grp * 64 + col] = hr_;
        }
    }
    __syncthreads();
    if (tid < 128) {
        float h = bc1[tid];
#pragma unroll
        for (int g = 0; g < 8; g++) h += hidp[g * 128 + tid];
        hid[tid] = fmaxf(h, 0.0f);
    }
    if (tid >= 128 && tid < 192) {
        int t = tid - 128;
        float h = bs1[t];
#pragma unroll
        for (int g = 0; g < 8; g++) h += hsp[g * 64 + t];
        hs[t] = fmaxf(h, 0.0f);
    }
    __syncthreads();

    // output dots: one warp per output, shuffle tree
    if (tid < 96) {
        const int wq = tid >> 5, lane = tid & 31;
        if (wq < 2) {
            float s = 0.f;
#pragma unroll
            for (int j = 0; j < 4; j++)
                s = fmaf(hid[lane + j * 32], Wc2[(lane + j * 32) * 2 + wq], s);
#pragma unroll
            for (int off = 16; off; off >>= 1) s += __shfl_xor_sync(0xffffffffu, s, off);
            if (lane == 0) out[bag * 2 + wq] = s + bc2[wq];
        } else {
            float r = 0.f;
#pragma unroll
            for (int j = 0; j < 2; j++)
                r = fmaf(hs[lane + j * 32], Ws2[lane + j * 32], r);
#pragma unroll
            for (int off = 16; off; off >>= 1) r += __shfl_xor_sync(0xffffffffu, r, off);
            if (lane == 0) out[16 + bag] = r + bs2[0];
        }
    }
}

extern "C" void kernel_launch(void* const* d_in, const int* in_sizes, int n_in,
                              void* d_out, int out_size)
{
    const float* x   = (const float*)d_in[0];
    const float* W1  = (const float*)d_in[1];
    const float* b1  = (const float*)d_in[2];
    const float* g1  = (const float*)d_in[3];
    const float* be1 = (const float*)d_in[4];
    const float* W2  = (const float*)d_in[5];
    const float* b2  = (const float*)d_in[6];
    const float* g2  = (const float*)d_in[7];
    const float* be2 = (const float*)d_in[8];
    const float* Wa1 = (const float*)d_in[9];
    const float* ba1 = (const float*)d_in[10];
    const float* Wa2 = (const float*)d_in[11];
    const float* ba2 = (const float*)d_in[12];
    const float* Wc1 = (const float*)d_in[13];
    const float* bc1 = (const float*)d_in[14];
    const float* Wc2 = (const float*)d_in[15];
    const float* bc2 = (const float*)d_in[16];
    const float* Ws1 = (const float*)d_in[17];
    const float* bs1 = (const float*)d_in[18];
    const float* Ws2 = (const float*)d_in[19];
    const float* bs2 = (const float*)d_in[20];
    float* out = (float*)d_out;

    cudaFuncSetAttribute(k_rows_mma, cudaFuncAttributeMaxDynamicSharedMemorySize, SMEM_SZ);

    k_prep<<<4, 256>>>(W1, W2, Wa1);
    k_rows_mma<<<MROWS / 128, 256, SMEM_SZ>>>(x, b1, g1, be1, b2, g2, be2, ba1, ba2, Wa2);
    k_wsum<<<NBAG * NCHUNK3, 256>>>();
    k_final<<<NBAG, 1024>>>(Wc1, bc1, Wc2, bc2, Ws1, bs1, Ws2, bs2, out);
}